// round 14
// baseline (speedup 1.0000x reference)
#include <cuda_runtime.h>
#include <cuda_fp16.h>
#include <cstdint>

#define Bb 2
#define Nn 128
#define Cc 256
#define BN2 (Bb*Nn*Nn)        // 32768 edge rows
#define NODES_SZ (Bb*Nn*Cc)   // 65536
#define EDGES_SZ (BN2*Cc)     // 8388608
#define KN_ 101
#define KE_ 7
#define ALPHA 0.2f
#define LN_EPS 1e-5f
#define NEG_BIG (-1e30f)

// ---------------- scratch (device globals: allocation-free) ----------------
__device__ float g_eA[EDGES_SZ];
__device__ float g_eB[EDGES_SZ];
__device__ __half g_ehA[EDGES_SZ];     // fp16 shadows of edge activations
__device__ __half g_ehB[EDGES_SZ];
__device__ __half g_wh[3 * Cc * Cc];   // fp16 Wb2 slices, all 3 layers
__device__ float g_n0[NODES_SZ];
__device__ float g_n1[NODES_SZ];
__device__ float g_ai[NODES_SZ];
__device__ float g_aj[NODES_SZ];
__device__ float g_nf[NODES_SZ];
__device__ float g_s[Bb*Nn];
__device__ float g_v[Cc];
__device__ float g_w[Cc];
__device__ float g_dotv[BN2];

// ---------------- fp16 helpers ---------------------------------------------
__device__ __forceinline__ uint2 f2h4(float4 v)
{
    __half2 lo = __floats2half2_rn(v.x, v.y);
    __half2 hi = __floats2half2_rn(v.z, v.w);
    uint2 r;
    r.x = *(unsigned*)&lo;
    r.y = *(unsigned*)&hi;
    return r;
}
__device__ __forceinline__ void mma16n8k16(float& c0, float& c1, float& c2, float& c3,
                                           unsigned a0, unsigned a1, unsigned a2, unsigned a3,
                                           unsigned b0, unsigned b1)
{
    asm volatile("mma.sync.aligned.m16n8k16.row.col.f32.f16.f16.f32 "
                 "{%0,%1,%2,%3}, {%4,%5,%6,%7}, {%8,%9}, {%0,%1,%2,%3};"
                 : "+f"(c0), "+f"(c1), "+f"(c2), "+f"(c3)
                 : "r"(a0), "r"(a1), "r"(a2), "r"(a3), "r"(b0), "r"(b1));
}
__device__ __forceinline__ void ldsm_x4(unsigned r[4], uint32_t addr)
{
    asm volatile("ldmatrix.sync.aligned.m8n8.x4.shared.b16 {%0,%1,%2,%3}, [%4];"
                 : "=r"(r[0]), "=r"(r[1]), "=r"(r[2]), "=r"(r[3]) : "r"(addr));
}
__device__ __forceinline__ uint32_t smem_u32(const void* p)
{
    uint32_t a;
    asm("{ .reg .u64 t; cvta.to.shared.u64 t, %1; cvt.u32.u64 %0, t; }"
        : "=r"(a) : "l"(p));
    return a;
}
__device__ __forceinline__ void cp16(uint32_t dst, const void* src)
{
    asm volatile("cp.async.cg.shared.global [%0], [%1], 16;"
                 :: "r"(dst), "l"(src) : "memory");
}
#define CP_COMMIT() asm volatile("cp.async.commit_group;" ::: "memory")
#define CP_WAIT2()  asm volatile("cp.async.wait_group 2;" ::: "memory")
#define CP_WAIT0()  asm volatile("cp.async.wait_group 0;" ::: "memory")

// 80-byte rows (32 halves data + pad): bank walk conflict-free for LDSM
#define HSTR 20
#define HROWB 80

// ---------------- small generic GEMM: out[m,n] = A[m,:]·W[n,:] + bias ------
__global__ void gemm_small(const float* __restrict__ A, const float* __restrict__ W,
                           const float* __restrict__ bias, float* __restrict__ out,
                           int M, int N, int K, int ldw)
{
    __shared__ float As[16][16];
    __shared__ float Ws[16][17];
    int tx = threadIdx.x, ty = threadIdx.y;
    int m = blockIdx.y * 16 + ty;
    int n = blockIdx.x * 16 + tx;
    float acc = 0.f;
    for (int k0 = 0; k0 < K; k0 += 16) {
        As[ty][tx] = (m < M) ? A[m * K + k0 + tx] : 0.f;
        int nn = blockIdx.x * 16 + ty;
        Ws[ty][tx] = (nn < N) ? W[(size_t)nn * ldw + k0 + tx] : 0.f;
        __syncthreads();
#pragma unroll
        for (int kk = 0; kk < 16; kk++) acc += As[ty][kk] * Ws[tx][kk];
        __syncthreads();
    }
    if (m < M && n < N) {
        float b = bias ? bias[n] : 0.f;
        out[m * N + n] = acc + b;
    }
}

// ---------------- W -> fp16 conversion (all 3 layers, once) ----------------
__global__ void wcvt_kernel(const float* __restrict__ Wb, __half* __restrict__ wh)
{
    int idx = blockIdx.x * 256 + threadIdx.x;   // 768 blocks -> 196608
    int l = idx >> 16;
    int r = idx & 65535;
    int n = r >> 8, k = r & 255;
    wh[idx] = __float2half(Wb[(size_t)l * 256 * 768 + (size_t)n * 768 + 256 + k]);
}

// ---------------- edge projection GEMM (K=64): 512 thr, 128x128, LDSM ------
// writes f32 output + fp16 shadow
__global__ void __launch_bounds__(512)
edge_proj_mma(const float* __restrict__ A, const float* __restrict__ W,
              int K, int ldw, const float* __restrict__ bias,
              float* __restrict__ out, __half* __restrict__ outh)
{
    __shared__ unsigned As[128 * HSTR];
    __shared__ unsigned Bs[128 * HSTR];
    int tid = threadIdx.x;
    int lane = tid & 31, wid = tid >> 5;
    int warp_m = (wid & 3) * 32;
    int warp_n = (wid >> 2) * 32;
    int mbase = blockIdx.y * 128;
    int nbase = blockIdx.x * 128;
    int lg = lane >> 2, lt = lane & 3;

    float c[2][4][4];
#pragma unroll
    for (int mi = 0; mi < 2; mi++)
#pragma unroll
        for (int ni = 0; ni < 4; ni++)
#pragma unroll
            for (int q = 0; q < 4; q++) c[mi][ni][q] = 0.f;

    int lrow = tid >> 2;
    int lkw = (tid & 3) * 4;
    const float* Aptr = A + (size_t)(mbase + lrow) * K + lkw * 2;
    const float* Wptr = W + (size_t)(nbase + lrow) * ldw + lkw * 2;
    unsigned* asw = &As[lrow * HSTR + lkw];
    unsigned* bsw = &Bs[lrow * HSTR + lkw];

    uint32_t abase = smem_u32(As), bbase = smem_u32(Bs);
    uint32_t a_off = (uint32_t)(warp_m + (lane & 15)) * HROWB + (lane >> 4) * 16;
    uint32_t b_off = (uint32_t)(warp_n + ((lane >> 4) << 3) + (lane & 7)) * HROWB
                   + ((lane >> 3) & 1) * 16;

    float4 ra[2], rb[2];
#pragma unroll
    for (int q = 0; q < 2; q++) {
        ra[q] = *(const float4*)(Aptr + 4 * q);
        rb[q] = *(const float4*)(Wptr + 4 * q);
    }

    for (int kt = 0; kt < K; kt += 32) {
#pragma unroll
        for (int q = 0; q < 2; q++) {
            *(uint2*)(asw + 2 * q) = f2h4(ra[q]);
            *(uint2*)(bsw + 2 * q) = f2h4(rb[q]);
        }
        __syncthreads();
        if (kt + 32 < K) {
#pragma unroll
            for (int q = 0; q < 2; q++) {
                ra[q] = *(const float4*)(Aptr + kt + 32 + 4 * q);
                rb[q] = *(const float4*)(Wptr + kt + 32 + 4 * q);
            }
        }
        unsigned af[2][2][4], bf[2][2][4];
#pragma unroll
        for (int mi = 0; mi < 2; mi++)
#pragma unroll
            for (int ks = 0; ks < 2; ks++)
                ldsm_x4(af[mi][ks], abase + a_off + mi * 16 * HROWB + ks * 32);
#pragma unroll
        for (int p = 0; p < 2; p++)
#pragma unroll
            for (int ks = 0; ks < 2; ks++)
                ldsm_x4(bf[p][ks], bbase + b_off + p * 16 * HROWB + ks * 32);
#pragma unroll
        for (int ks = 0; ks < 2; ks++)
#pragma unroll
            for (int mi = 0; mi < 2; mi++)
#pragma unroll
                for (int p = 0; p < 2; p++) {
                    mma16n8k16(c[mi][2*p][0], c[mi][2*p][1], c[mi][2*p][2], c[mi][2*p][3],
                               af[mi][ks][0], af[mi][ks][1], af[mi][ks][2], af[mi][ks][3],
                               bf[p][ks][0], bf[p][ks][1]);
                    mma16n8k16(c[mi][2*p+1][0], c[mi][2*p+1][1], c[mi][2*p+1][2], c[mi][2*p+1][3],
                               af[mi][ks][0], af[mi][ks][1], af[mi][ks][2], af[mi][ks][3],
                               bf[p][ks][2], bf[p][ks][3]);
                }
        __syncthreads();
    }

#pragma unroll
    for (int mi = 0; mi < 2; mi++)
#pragma unroll
        for (int half = 0; half < 2; half++) {
            int m = mbase + warp_m + mi * 16 + lg + half * 8;
#pragma unroll
            for (int ni = 0; ni < 4; ni++) {
                int col = nbase + warp_n + ni * 8 + 2 * lt;
                float2 bv = *(const float2*)&bias[col];
                float o0 = c[mi][ni][2 * half + 0] + bv.x;
                float o1 = c[mi][ni][2 * half + 1] + bv.y;
                *(float2*)&out[(size_t)m * 256 + col] = make_float2(o0, o1);
                __half2 h2 = __floats2half2_rn(o0, o1);
                *(__half2*)&outh[(size_t)m * 256 + col] = h2;
            }
        }
}

// ---------------- node GEMMs: 64x64 tiles, 48 blocks, fp16 scalar-LDS ------
#define NSTR 18
__global__ void __launch_bounds__(128)
node3_mma(const float* __restrict__ A, const float* __restrict__ Wb_l,
          const float* __restrict__ Wf_l,
          float* __restrict__ ai, float* __restrict__ aj, float* __restrict__ nf)
{
    __shared__ unsigned As[64 * NSTR];
    __shared__ unsigned Bs[64 * NSTR];
    int z = blockIdx.z;
    const float* W = (z == 0) ? Wb_l : (z == 1) ? (Wb_l + 512) : Wf_l;
    int ldw = (z == 2) ? 256 : 768;
    float* out = (z == 0) ? ai : (z == 1) ? aj : nf;

    int tid = threadIdx.x;
    int lane = tid & 31, wid = tid >> 5;
    int warp_m = (wid & 1) * 32;
    int warp_n = (wid >> 1) * 32;
    int mbase = blockIdx.y * 64;
    int nbase = blockIdx.x * 64;
    int lg = lane >> 2, lt = lane & 3;

    float c[2][4][4];
#pragma unroll
    for (int mi = 0; mi < 2; mi++)
#pragma unroll
        for (int ni = 0; ni < 4; ni++)
#pragma unroll
            for (int q = 0; q < 4; q++) c[mi][ni][q] = 0.f;

    int lrow = tid >> 1;
    int lkw = (tid & 1) * 8;
    const float* Aptr = A + (size_t)(mbase + lrow) * 256 + lkw * 2;
    const float* Wptr = W + (size_t)(nbase + lrow) * ldw + lkw * 2;
    unsigned* asw = &As[lrow * NSTR + lkw];
    unsigned* bsw = &Bs[lrow * NSTR + lkw];

    float4 ra[4], rb[4];
#pragma unroll
    for (int q = 0; q < 4; q++) {
        ra[q] = *(const float4*)(Aptr + 4 * q);
        rb[q] = *(const float4*)(Wptr + 4 * q);
    }

    for (int kt = 0; kt < 256; kt += 32) {
#pragma unroll
        for (int q = 0; q < 4; q++) {
            *(uint2*)(asw + 2 * q) = f2h4(ra[q]);
            *(uint2*)(bsw + 2 * q) = f2h4(rb[q]);
        }
        __syncthreads();
        if (kt + 32 < 256) {
#pragma unroll
            for (int q = 0; q < 4; q++) {
                ra[q] = *(const float4*)(Aptr + kt + 32 + 4 * q);
                rb[q] = *(const float4*)(Wptr + kt + 32 + 4 * q);
            }
        }
#pragma unroll
        for (int ks = 0; ks < 2; ks++) {
            int kw = ks * 8 + lt;
            unsigned af[2][4], bf[4][2];
#pragma unroll
            for (int mi = 0; mi < 2; mi++) {
                int r0 = warp_m + mi * 16 + lg;
                af[mi][0] = As[r0 * NSTR + kw];
                af[mi][1] = As[(r0 + 8) * NSTR + kw];
                af[mi][2] = As[r0 * NSTR + kw + 4];
                af[mi][3] = As[(r0 + 8) * NSTR + kw + 4];
            }
#pragma unroll
            for (int ni = 0; ni < 4; ni++) {
                int n0 = warp_n + ni * 8 + lg;
                bf[ni][0] = Bs[n0 * NSTR + kw];
                bf[ni][1] = Bs[n0 * NSTR + kw + 4];
            }
#pragma unroll
            for (int mi = 0; mi < 2; mi++)
#pragma unroll
                for (int ni = 0; ni < 4; ni++)
                    mma16n8k16(c[mi][ni][0], c[mi][ni][1], c[mi][ni][2], c[mi][ni][3],
                               af[mi][0], af[mi][1], af[mi][2], af[mi][3],
                               bf[ni][0], bf[ni][1]);
        }
        __syncthreads();
    }

#pragma unroll
    for (int mi = 0; mi < 2; mi++)
#pragma unroll
        for (int half = 0; half < 2; half++) {
            int m = mbase + warp_m + mi * 16 + lg + half * 8;
#pragma unroll
            for (int ni = 0; ni < 4; ni++) {
                int col = nbase + warp_n + ni * 8 + 2 * lt;
                *(float2*)&out[(size_t)m * 256 + col] =
                    make_float2(c[mi][ni][2 * half + 0], c[mi][ni][2 * half + 1]);
            }
        }
}

// ---------------- FUSED edge layer: cp.async 4-stage fp16 pipeline ---------
// Tile 64 rows x 256 cols. 16 warps as 2m x 8n, warp tile 32x32.
// A (fp16 shadow) + W (fp16) streamed via cp.async; residual/epilogue in f32.
#define STG 4
#define ABY (64 * HROWB)      // 5120 B per stage
#define BBY (256 * HROWB)     // 20480 B per stage
#define EF_DSMEM (STG * (ABY + BBY))   // 102400 B
__global__ void __launch_bounds__(512)
edge_fused(const __half* __restrict__ Ah, const float* __restrict__ A32,
           const __half* __restrict__ Wh,
           const float* __restrict__ ai, const float* __restrict__ aj,
           const float* __restrict__ mask,
           const float* __restrict__ lng, const float* __restrict__ lnb,
           const float* __restrict__ v,
           float* __restrict__ out, __half* __restrict__ outh,
           float* __restrict__ dotv)
{
    extern __shared__ char dyn[];
    uint32_t aS = smem_u32(dyn);               // STG A stages
    uint32_t bS = aS + STG * ABY;              // STG B stages
    float* red = (float*)dyn;

    int tid = threadIdx.x;
    int lane = tid & 31, wid = tid >> 5;
    int wm = wid & 1;
    int wn = wid >> 1;
    int warp_m = wm * 32;
    int warp_n = wn * 32;
    int mbase = blockIdx.x * 64;
    int lg = lane >> 2, lt = lane & 3;

    float c[2][4][4];
#pragma unroll
    for (int mi = 0; mi < 2; mi++)
#pragma unroll
        for (int ni = 0; ni < 4; ni++)
#pragma unroll
            for (int q = 0; q < 4; q++) c[mi][ni][q] = 0.f;

    uint32_t a_off = (uint32_t)(warp_m + (lane & 15)) * HROWB + (lane >> 4) * 16;
    uint32_t b_off = (uint32_t)(warp_n + ((lane >> 4) << 3) + (lane & 7)) * HROWB
                   + ((lane >> 3) & 1) * 16;

    // stage loader: A 64x32h (256 chunks), B 256x32h (1024 chunks)
    auto load_stage = [&](int slot, int kt) {
        if (tid < 256) {
            int row = tid >> 2, q = tid & 3;
            const __half* src = Ah + (size_t)(mbase + row) * 256 + kt + q * 8;
            cp16(aS + slot * ABY + row * HROWB + q * 16, src);
        }
#pragma unroll
        for (int it = 0; it < 2; it++) {
            int cidx = it * 512 + tid;
            int row = cidx >> 2, q = cidx & 3;
            const __half* src = Wh + (size_t)row * 256 + kt + q * 8;
            cp16(bS + slot * BBY + row * HROWB + q * 16, src);
        }
        CP_COMMIT();
    };

    // prologue: stages 0..2
    load_stage(0, 0);
    load_stage(1, 32);
    load_stage(2, 64);

    for (int t = 0; t < 8; t++) {
        CP_WAIT2();
        __syncthreads();
        int slot = t & (STG - 1);
        uint32_t ab = aS + slot * ABY;
        uint32_t bb = bS + slot * BBY;
        unsigned af[2][2][4], bf[2][2][4];
#pragma unroll
        for (int mi = 0; mi < 2; mi++)
#pragma unroll
            for (int ks = 0; ks < 2; ks++)
                ldsm_x4(af[mi][ks], ab + a_off + mi * 16 * HROWB + ks * 32);
#pragma unroll
        for (int p = 0; p < 2; p++)
#pragma unroll
            for (int ks = 0; ks < 2; ks++)
                ldsm_x4(bf[p][ks], bb + b_off + p * 16 * HROWB + ks * 32);
#pragma unroll
        for (int ks = 0; ks < 2; ks++)
#pragma unroll
            for (int mi = 0; mi < 2; mi++)
#pragma unroll
                for (int p = 0; p < 2; p++) {
                    mma16n8k16(c[mi][2*p][0], c[mi][2*p][1], c[mi][2*p][2], c[mi][2*p][3],
                               af[mi][ks][0], af[mi][ks][1], af[mi][ks][2], af[mi][ks][3],
                               bf[p][ks][0], bf[p][ks][1]);
                    mma16n8k16(c[mi][2*p+1][0], c[mi][2*p+1][1], c[mi][2*p+1][2], c[mi][2*p+1][3],
                               af[mi][ks][0], af[mi][ks][1], af[mi][ks][2], af[mi][ks][3],
                               bf[p][ks][2], bf[p][ks][3]);
                }
        int nt = t + STG - 1;
        if (nt < 8) load_stage(nt & (STG - 1), nt * 32);
        else        CP_COMMIT();           // empty group keeps wait count uniform
    }
    CP_WAIT0();
    __syncthreads();

    // ---- epilogue phase 1: h = lrelu(acc+ai+aj)*mask + residual; row stats
#pragma unroll
    for (int mi = 0; mi < 2; mi++) {
#pragma unroll
        for (int half = 0; half < 2; half++) {
            int rloc = warp_m + mi * 16 + half * 8 + lg;
            int m = mbase + rloc;
            int b = m >> 14;
            int i = (m >> 7) & 127;
            int j = m & 127;
            float mv = mask[m];
            const float* aip = &ai[(size_t)((b << 7) + i) * 256];
            const float* ajp = &aj[(size_t)((b << 7) + j) * 256];
            const float* res = &A32[(size_t)m * 256];
            float rs = 0.f, rq = 0.f;
#pragma unroll
            for (int ni = 0; ni < 4; ni++) {
                int col = warp_n + ni * 8 + 2 * lt;
                float2 a2 = *(const float2*)&aip[col];
                float2 j2 = *(const float2*)&ajp[col];
                float2 r2 = *(const float2*)&res[col];
                float v0 = c[mi][ni][2 * half + 0] + a2.x + j2.x;
                float v1 = c[mi][ni][2 * half + 1] + a2.y + j2.y;
                v0 = (v0 > 0.f ? v0 : ALPHA * v0) * mv + r2.x;
                v1 = (v1 > 0.f ? v1 : ALPHA * v1) * mv + r2.y;
                c[mi][ni][2 * half + 0] = v0;
                c[mi][ni][2 * half + 1] = v1;
                rs += v0 + v1;
                rq += v0 * v0 + v1 * v1;
            }
            rs += __shfl_xor_sync(0xffffffffu, rs, 1);
            rs += __shfl_xor_sync(0xffffffffu, rs, 2);
            rq += __shfl_xor_sync(0xffffffffu, rq, 1);
            rq += __shfl_xor_sync(0xffffffffu, rq, 2);
            if (lt == 0) {
                red[wn * 64 + rloc] = rs;
                red[512 + wn * 64 + rloc] = rq;
            }
        }
    }
    __syncthreads();
    if (tid < 64) {
        float S = 0.f, Q = 0.f;
#pragma unroll
        for (int w8 = 0; w8 < 8; w8++) {
            S += red[w8 * 64 + tid];
            Q += red[512 + w8 * 64 + tid];
        }
        float mean = S * (1.f / 256.f);
        float var = Q * (1.f / 256.f) - mean * mean;
        red[1024 + tid] = mean;
        red[1088 + tid] = rsqrtf(var + LN_EPS);
    }
    __syncthreads();

    // ---- epilogue phase 2: normalize, store f32 + f16 shadow, dot with v
#pragma unroll
    for (int mi = 0; mi < 2; mi++) {
#pragma unroll
        for (int half = 0; half < 2; half++) {
            int rloc = warp_m + mi * 16 + half * 8 + lg;
            int m = mbase + rloc;
            float mean = red[1024 + rloc];
            float inv = red[1088 + rloc];
            float dvp = 0.f;
#pragma unroll
            for (int ni = 0; ni < 4; ni++) {
                int col = warp_n + ni * 8 + 2 * lt;
                float2 g2 = *(const float2*)&lng[col];
                float2 b2 = *(const float2*)&lnb[col];
                float2 v2 = *(const float2*)&v[col];
                float y0 = (c[mi][ni][2 * half + 0] - mean) * inv * g2.x + b2.x;
                float y1 = (c[mi][ni][2 * half + 1] - mean) * inv * g2.y + b2.y;
                *(float2*)&out[(size_t)m * 256 + col] = make_float2(y0, y1);
                *(__half2*)&outh[(size_t)m * 256 + col] = __floats2half2_rn(y0, y1);
                dvp += y0 * v2.x + y1 * v2.y;
            }
            dvp += __shfl_xor_sync(0xffffffffu, dvp, 1);
            dvp += __shfl_xor_sync(0xffffffffu, dvp, 2);
            if (lt == 0) red[wn * 64 + rloc] = dvp;
        }
    }
    __syncthreads();
    if (tid < 64) {
        float S = 0.f;
#pragma unroll
        for (int w8 = 0; w8 < 8; w8++) S += red[w8 * 64 + tid];
        dotv[mbase + tid] = S;
    }
}

// ---------------- v = Wbp^T ub, w = Wfp^T ub, s = nodes·w (merged) ---------
__global__ void vws_kernel(const float* __restrict__ Wbp, const float* __restrict__ Wfp,
                           const float* __restrict__ ub, const float* __restrict__ nodes,
                           float* __restrict__ v, float* __restrict__ w,
                           float* __restrict__ s)
{
    __shared__ float ws[256];
    int k = threadIdx.x;
    float a = 0.f, b = 0.f;
    for (int c = 0; c < 256; c++) {
        float u = ub[c];
        a += u * Wbp[c * 256 + k];
        b += u * Wfp[c * 256 + k];
    }
    v[k] = a; w[k] = b;
    ws[k] = b;
    __syncthreads();
    float acc = 0.f;
    const float* rp = nodes + (size_t)k * 256;
    for (int c = 0; c < 256; c++) acc += rp[c] * ws[c];
    s[k] = acc;
}

// ---------------- attention + node update (LN fused) -----------------------
__global__ void __launch_bounds__(256)
attn_kernel(const float* __restrict__ dotv, const float* __restrict__ s,
            const float* __restrict__ nf, const float* __restrict__ mask,
            const float* __restrict__ nodes_old, const float* __restrict__ g,
            const float* __restrict__ bt, float* __restrict__ nodes_new)
{
    int bi = blockIdx.x;
    int b = bi >> 7, i = bi & 127;
    int t = threadIdx.x;
    __shared__ float sm_a[128];
    __shared__ float sred1[8], sred2[8];
    __shared__ float sm_m, sm_sum, sm_mean, sm_inv;

    if (t < 128) {
        int j = t;
        float mv = mask[b * 16384 + i * 128 + j];
        float r;
        if (mv > 0.f) {
            float dv = dotv[b * 16384 + j * 128 + i];
            r = dv + s[b * 128 + i] + s[b * 128 + j];
            r = r > 0.f ? r : ALPHA * r;
        } else {
            r = NEG_BIG;
        }
        sm_a[j] = r;
    }
    __syncthreads();
    if (t < 32) {
        float m = fmaxf(fmaxf(sm_a[t], sm_a[t + 32]), fmaxf(sm_a[t + 64], sm_a[t + 96]));
#pragma unroll
        for (int o = 16; o; o >>= 1) m = fmaxf(m, __shfl_xor_sync(0xffffffffu, m, o));
        if (t == 0) sm_m = m;
    }
    __syncthreads();
    if (t < 128) sm_a[t] = expf(sm_a[t] - sm_m);
    __syncthreads();
    if (t < 32) {
        float su = sm_a[t] + sm_a[t + 32] + sm_a[t + 64] + sm_a[t + 96];
#pragma unroll
        for (int o = 16; o; o >>= 1) su += __shfl_xor_sync(0xffffffffu, su, o);
        if (t == 0) sm_sum = su;
    }
    __syncthreads();
    float inv_sum = 1.f / sm_sum;

    int c = t;
    float acc = 0.f;
    const float* nfb = nf + (size_t)b * Nn * Cc + c;
#pragma unroll 4
    for (int j = 0; j < 128; j++) acc += sm_a[j] * nfb[(size_t)j * Cc];
    acc *= inv_sum;
    float h = (acc > 0.f ? acc : ALPHA * acc) + nodes_old[(size_t)(b * 128 + i) * 256 + c];

    int lane = t & 31, wp = t >> 5;
    float su = h, sq = h * h;
#pragma unroll
    for (int o = 16; o; o >>= 1) {
        su += __shfl_xor_sync(0xffffffffu, su, o);
        sq += __shfl_xor_sync(0xffffffffu, sq, o);
    }
    if (lane == 0) { sred1[wp] = su; sred2[wp] = sq; }
    __syncthreads();
    if (t == 0) {
        float S = 0.f, Q = 0.f;
#pragma unroll
        for (int w2 = 0; w2 < 8; w2++) { S += sred1[w2]; Q += sred2[w2]; }
        float mean = S * (1.f / 256.f);
        float var = Q * (1.f / 256.f) - mean * mean;
        sm_mean = mean;
        sm_inv = rsqrtf(var + LN_EPS);
    }
    __syncthreads();
    nodes_new[(size_t)(b * 128 + i) * 256 + c] = (h - sm_mean) * sm_inv * g[c] + bt[c];
}

// ---------------- edge logits: out[row,k] = e[row]·ecW[k] + ecb[k] ---------
__global__ void edge_logits_kernel(const float* __restrict__ e, const float* __restrict__ W,
                                   const float* __restrict__ bias, float* __restrict__ out)
{
    int warp = threadIdx.x >> 5, lane = threadIdx.x & 31;
    int row = blockIdx.x * 8 + warp;
    const float* rp = e + (size_t)row * 256;
    float x[8];
#pragma unroll
    for (int q = 0; q < 8; q++) x[q] = rp[lane + q * 32];
#pragma unroll
    for (int k = 0; k < KE_; k++) {
        float acc = 0.f;
#pragma unroll
        for (int q = 0; q < 8; q++) acc += x[q] * W[k * 256 + lane + q * 32];
#pragma unroll
        for (int o = 16; o; o >>= 1) acc += __shfl_xor_sync(0xffffffffu, acc, o);
        if (lane == 0) out[(size_t)row * KE_ + k] = acc + bias[k];
    }
}

// ---------------- host ------------------------------------------------------
extern "C" void kernel_launch(void* const* d_in, const int* in_sizes, int n_in,
                              void* d_out, int out_size)
{
    const float* nodes_in = (const float*)d_in[0];
    const float* edges_in = (const float*)d_in[1];
    const float* adj      = (const float*)d_in[2];
    const float* pnW = (const float*)d_in[3];
    const float* pnb = (const float*)d_in[4];
    const float* peW = (const float*)d_in[5];
    const float* peb = (const float*)d_in[6];
    const float* Wb  = (const float*)d_in[7];
    const float* Wbp = (const float*)d_in[8];
    const float* Wfp = (const float*)d_in[9];
    const float* ub  = (const float*)d_in[10];
    const float* Wf  = (const float*)d_in[11];
    const float* eln_g = (const float*)d_in[12];
    const float* eln_b = (const float*)d_in[13];
    const float* nln_g = (const float*)d_in[14];
    const float* nln_b = (const float*)d_in[15];
    const float* ncW = (const float*)d_in[16];
    const float* ncb = (const float*)d_in[17];
    const float* ecW = (const float*)d_in[18];
    const float* ecb = (const float*)d_in[19];

    float *eA, *eB, *n0, *n1, *ai_, *aj_, *nf_, *s_, *v_, *w_, *dv_;
    __half *ehA, *ehB, *wh_;
    cudaGetSymbolAddress((void**)&eA, g_eA);
    cudaGetSymbolAddress((void**)&eB, g_eB);
    cudaGetSymbolAddress((void**)&ehA, g_ehA);
    cudaGetSymbolAddress((void**)&ehB, g_ehB);
    cudaGetSymbolAddress((void**)&wh_, g_wh);
    cudaGetSymbolAddress((void**)&n0, g_n0);
    cudaGetSymbolAddress((void**)&n1, g_n1);
    cudaGetSymbolAddress((void**)&ai_, g_ai);
    cudaGetSymbolAddress((void**)&aj_, g_aj);
    cudaGetSymbolAddress((void**)&nf_, g_nf);
    cudaGetSymbolAddress((void**)&s_, g_s);
    cudaGetSymbolAddress((void**)&v_, g_v);
    cudaGetSymbolAddress((void**)&w_, g_w);
    cudaGetSymbolAddress((void**)&dv_, g_dotv);

    cudaFuncSetAttribute(edge_fused, cudaFuncAttributeMaxDynamicSharedMemorySize,
                         EF_DSMEM);

    float* out = (float*)d_out;
    float* out_nodes = out;
    float* out_edges = out + NODES_SZ;

    // ping-pong; layer 2 writes land directly in d_out (no copies)
    float* ebuf[4] = {eA, eB, eA, out_edges};
    float* nbuf[4] = {n0, n1, n0, out_nodes};
    __half* ehbuf[4] = {ehA, ehB, ehA, ehB};   // layer-2 shadow unused, harmless

    dim3 bs(16, 16);

    // weights -> fp16 (constants; once) + initial projections
    wcvt_kernel<<<768, 256>>>(Wb, wh_);
    gemm_small<<<dim3(16, 16), bs>>>(nodes_in, pnW, pnb, nbuf[0], 256, 256, 128, 128);
    edge_proj_mma<<<dim3(2, 256), 512>>>(edges_in, peW, 64, 64, peb, ebuf[0], ehbuf[0]);

    for (int l = 0; l < 3; l++) {
        const float* Wb_l  = Wb  + (size_t)l * 256 * 768;
        const float* Wbp_l = Wbp + (size_t)l * 65536;
        const float* Wfp_l = Wfp + (size_t)l * 65536;
        const float* ub_l  = ub  + l * 256;
        const float* Wf_l  = Wf  + (size_t)l * 65536;
        float* ecur = ebuf[l]; float* enxt = ebuf[l + 1];
        float* ncur = nbuf[l]; float* nnxt = nbuf[l + 1];

        vws_kernel<<<1, 256>>>(Wbp_l, Wfp_l, ub_l, ncur, v_, w_, s_);
        node3_mma<<<dim3(4, 4, 3), 128>>>(ncur, Wb_l, Wf_l, ai_, aj_, nf_);

        edge_fused<<<512, 512, EF_DSMEM>>>(ehbuf[l], ecur, wh_ + (size_t)l * 65536,
                                           ai_, aj_, adj,
                                           eln_g + l * 256, eln_b + l * 256, v_,
                                           enxt, ehbuf[l + 1], dv_);
        attn_kernel<<<256, 256>>>(dv_, s_, nf_, adj, ncur,
                                  nln_g + l * 256, nln_b + l * 256, nnxt);
    }

    // final heads read directly from d_out regions
    gemm_small<<<dim3(7, 16), bs>>>(nbuf[3], ncW, ncb, out + NODES_SZ + EDGES_SZ,
                                    256, KN_, 256, 256);
    edge_logits_kernel<<<4096, 256>>>(ebuf[3], ecW, ecb,
                                      out + NODES_SZ + EDGES_SZ + 256 * KN_);
}

// round 16
// speedup vs baseline: 1.6553x; 1.6553x over previous
#include <cuda_runtime.h>
#include <cuda_fp16.h>
#include <cstdint>

#define Bb 2
#define Nn 128
#define Cc 256
#define BN2 (Bb*Nn*Nn)        // 32768 edge rows
#define NODES_SZ (Bb*Nn*Cc)   // 65536
#define EDGES_SZ (BN2*Cc)     // 8388608
#define KN_ 101
#define KE_ 7
#define ALPHA 0.2f
#define LN_EPS 1e-5f
#define NEG_BIG (-1e30f)

// ---------------- scratch (device globals: allocation-free) ----------------
__device__ float g_eA[EDGES_SZ];
__device__ float g_eB[EDGES_SZ];
__device__ float g_n0[NODES_SZ];
__device__ float g_n1[NODES_SZ];
__device__ float g_ai[NODES_SZ];
__device__ float g_aj[NODES_SZ];
__device__ float g_nf[NODES_SZ];
__device__ float g_s[Bb*Nn];
__device__ float g_v[Cc];
__device__ float g_w[Cc];
__device__ float g_dotv[BN2];

// ---------------- fp16 helpers ---------------------------------------------
__device__ __forceinline__ uint2 f2h4(float4 v)
{
    __half2 lo = __floats2half2_rn(v.x, v.y);
    __half2 hi = __floats2half2_rn(v.z, v.w);
    uint2 r;
    r.x = *(unsigned*)&lo;
    r.y = *(unsigned*)&hi;
    return r;
}
__device__ __forceinline__ void mma16n8k16(float& c0, float& c1, float& c2, float& c3,
                                           unsigned a0, unsigned a1, unsigned a2, unsigned a3,
                                           unsigned b0, unsigned b1)
{
    asm volatile("mma.sync.aligned.m16n8k16.row.col.f32.f16.f16.f32 "
                 "{%0,%1,%2,%3}, {%4,%5,%6,%7}, {%8,%9}, {%0,%1,%2,%3};"
                 : "+f"(c0), "+f"(c1), "+f"(c2), "+f"(c3)
                 : "r"(a0), "r"(a1), "r"(a2), "r"(a3), "r"(b0), "r"(b1));
}
__device__ __forceinline__ void ldsm_x4(unsigned r[4], uint32_t addr)
{
    asm volatile("ldmatrix.sync.aligned.m8n8.x4.shared.b16 {%0,%1,%2,%3}, [%4];"
                 : "=r"(r[0]), "=r"(r[1]), "=r"(r[2]), "=r"(r[3]) : "r"(addr));
}
__device__ __forceinline__ uint32_t smem_u32(const void* p)
{
    uint32_t a;
    asm("{ .reg .u64 t; cvta.to.shared.u64 t, %1; cvt.u32.u64 %0, t; }"
        : "=r"(a) : "l"(p));
    return a;
}

// 80-byte rows (32 halves data + pad): bank walk conflict-free for LDSM
#define HSTR 20
#define HROWB 80
// scalar-LDS node kernel stride
#define NSTR 18

// ---------------- small generic GEMM: out[m,n] = A[m,:]·W[n,:] + bias ------
__global__ void gemm_small(const float* __restrict__ A, const float* __restrict__ W,
                           const float* __restrict__ bias, float* __restrict__ out,
                           int M, int N, int K, int ldw)
{
    __shared__ float As[16][16];
    __shared__ float Ws[16][17];
    int tx = threadIdx.x, ty = threadIdx.y;
    int m = blockIdx.y * 16 + ty;
    int n = blockIdx.x * 16 + tx;
    float acc = 0.f;
    for (int k0 = 0; k0 < K; k0 += 16) {
        As[ty][tx] = (m < M) ? A[m * K + k0 + tx] : 0.f;
        int nn = blockIdx.x * 16 + ty;
        Ws[ty][tx] = (nn < N) ? W[(size_t)nn * ldw + k0 + tx] : 0.f;
        __syncthreads();
#pragma unroll
        for (int kk = 0; kk < 16; kk++) acc += As[ty][kk] * Ws[tx][kk];
        __syncthreads();
    }
    if (m < M && n < N) {
        float b = bias ? bias[n] : 0.f;
        out[m * N + n] = acc + b;
    }
}

// ---------------- edge projection GEMM (K=64): 512 thr, 128x128, LDSM ------
__global__ void __launch_bounds__(512)
edge_proj_mma(const float* __restrict__ A, const float* __restrict__ W,
              int K, int ldw, const float* __restrict__ bias, float* __restrict__ out)
{
    __shared__ unsigned As[128 * HSTR];
    __shared__ unsigned Bs[128 * HSTR];
    int tid = threadIdx.x;
    int lane = tid & 31, wid = tid >> 5;
    int warp_m = (wid & 3) * 32;
    int warp_n = (wid >> 2) * 32;
    int mbase = blockIdx.y * 128;
    int nbase = blockIdx.x * 128;
    int lg = lane >> 2, lt = lane & 3;

    float c[2][4][4];
#pragma unroll
    for (int mi = 0; mi < 2; mi++)
#pragma unroll
        for (int ni = 0; ni < 4; ni++)
#pragma unroll
            for (int q = 0; q < 4; q++) c[mi][ni][q] = 0.f;

    int lrow = tid >> 2;
    int lkw = (tid & 3) * 4;
    const float* Aptr = A + (size_t)(mbase + lrow) * K + lkw * 2;
    const float* Wptr = W + (size_t)(nbase + lrow) * ldw + lkw * 2;
    unsigned* asw = &As[lrow * HSTR + lkw];
    unsigned* bsw = &Bs[lrow * HSTR + lkw];

    uint32_t abase = smem_u32(As), bbase = smem_u32(Bs);
    uint32_t a_off = (uint32_t)(warp_m + (lane & 15)) * HROWB + (lane >> 4) * 16;
    uint32_t b_off = (uint32_t)(warp_n + ((lane >> 4) << 3) + (lane & 7)) * HROWB
                   + ((lane >> 3) & 1) * 16;

    float4 ra[2], rb[2];
#pragma unroll
    for (int q = 0; q < 2; q++) {
        ra[q] = *(const float4*)(Aptr + 4 * q);
        rb[q] = *(const float4*)(Wptr + 4 * q);
    }

    for (int kt = 0; kt < K; kt += 32) {
#pragma unroll
        for (int q = 0; q < 2; q++) {
            *(uint2*)(asw + 2 * q) = f2h4(ra[q]);
            *(uint2*)(bsw + 2 * q) = f2h4(rb[q]);
        }
        __syncthreads();
        if (kt + 32 < K) {
#pragma unroll
            for (int q = 0; q < 2; q++) {
                ra[q] = *(const float4*)(Aptr + kt + 32 + 4 * q);
                rb[q] = *(const float4*)(Wptr + kt + 32 + 4 * q);
            }
        }
        unsigned af[2][2][4], bf[2][2][4];
#pragma unroll
        for (int mi = 0; mi < 2; mi++)
#pragma unroll
            for (int ks = 0; ks < 2; ks++)
                ldsm_x4(af[mi][ks], abase + a_off + mi * 16 * HROWB + ks * 32);
#pragma unroll
        for (int p = 0; p < 2; p++)
#pragma unroll
            for (int ks = 0; ks < 2; ks++)
                ldsm_x4(bf[p][ks], bbase + b_off + p * 16 * HROWB + ks * 32);
#pragma unroll
        for (int ks = 0; ks < 2; ks++)
#pragma unroll
            for (int mi = 0; mi < 2; mi++)
#pragma unroll
                for (int p = 0; p < 2; p++) {
                    mma16n8k16(c[mi][2*p][0], c[mi][2*p][1], c[mi][2*p][2], c[mi][2*p][3],
                               af[mi][ks][0], af[mi][ks][1], af[mi][ks][2], af[mi][ks][3],
                               bf[p][ks][0], bf[p][ks][1]);
                    mma16n8k16(c[mi][2*p+1][0], c[mi][2*p+1][1], c[mi][2*p+1][2], c[mi][2*p+1][3],
                               af[mi][ks][0], af[mi][ks][1], af[mi][ks][2], af[mi][ks][3],
                               bf[p][ks][2], bf[p][ks][3]);
                }
        __syncthreads();
    }

#pragma unroll
    for (int mi = 0; mi < 2; mi++)
#pragma unroll
        for (int half = 0; half < 2; half++) {
            int m = mbase + warp_m + mi * 16 + lg + half * 8;
#pragma unroll
            for (int ni = 0; ni < 4; ni++) {
                int col = nbase + warp_n + ni * 8 + 2 * lt;
                float2 bv = *(const float2*)&bias[col];
                *(float2*)&out[(size_t)m * 256 + col] =
                    make_float2(c[mi][ni][2 * half + 0] + bv.x,
                                c[mi][ni][2 * half + 1] + bv.y);
            }
        }
}

// ---------------- node GEMMs: 64x64 tiles, 48 blocks, fp16 scalar-LDS ------
__global__ void __launch_bounds__(128)
node3_mma(const float* __restrict__ A, const float* __restrict__ Wb_l,
          const float* __restrict__ Wf_l,
          float* __restrict__ ai, float* __restrict__ aj, float* __restrict__ nf)
{
    __shared__ unsigned As[64 * NSTR];
    __shared__ unsigned Bs[64 * NSTR];
    int z = blockIdx.z;
    const float* W = (z == 0) ? Wb_l : (z == 1) ? (Wb_l + 512) : Wf_l;
    int ldw = (z == 2) ? 256 : 768;
    float* out = (z == 0) ? ai : (z == 1) ? aj : nf;

    int tid = threadIdx.x;
    int lane = tid & 31, wid = tid >> 5;
    int warp_m = (wid & 1) * 32;
    int warp_n = (wid >> 1) * 32;
    int mbase = blockIdx.y * 64;
    int nbase = blockIdx.x * 64;
    int lg = lane >> 2, lt = lane & 3;

    float c[2][4][4];
#pragma unroll
    for (int mi = 0; mi < 2; mi++)
#pragma unroll
        for (int ni = 0; ni < 4; ni++)
#pragma unroll
            for (int q = 0; q < 4; q++) c[mi][ni][q] = 0.f;

    int lrow = tid >> 1;
    int lkw = (tid & 1) * 8;
    const float* Aptr = A + (size_t)(mbase + lrow) * 256 + lkw * 2;
    const float* Wptr = W + (size_t)(nbase + lrow) * ldw + lkw * 2;
    unsigned* asw = &As[lrow * NSTR + lkw];
    unsigned* bsw = &Bs[lrow * NSTR + lkw];

    float4 ra[4], rb[4];
#pragma unroll
    for (int q = 0; q < 4; q++) {
        ra[q] = *(const float4*)(Aptr + 4 * q);
        rb[q] = *(const float4*)(Wptr + 4 * q);
    }

    for (int kt = 0; kt < 256; kt += 32) {
#pragma unroll
        for (int q = 0; q < 4; q++) {
            *(uint2*)(asw + 2 * q) = f2h4(ra[q]);
            *(uint2*)(bsw + 2 * q) = f2h4(rb[q]);
        }
        __syncthreads();
        if (kt + 32 < 256) {
#pragma unroll
            for (int q = 0; q < 4; q++) {
                ra[q] = *(const float4*)(Aptr + kt + 32 + 4 * q);
                rb[q] = *(const float4*)(Wptr + kt + 32 + 4 * q);
            }
        }
#pragma unroll
        for (int ks = 0; ks < 2; ks++) {
            int kw = ks * 8 + lt;
            unsigned af[2][4], bf[4][2];
#pragma unroll
            for (int mi = 0; mi < 2; mi++) {
                int r0 = warp_m + mi * 16 + lg;
                af[mi][0] = As[r0 * NSTR + kw];
                af[mi][1] = As[(r0 + 8) * NSTR + kw];
                af[mi][2] = As[r0 * NSTR + kw + 4];
                af[mi][3] = As[(r0 + 8) * NSTR + kw + 4];
            }
#pragma unroll
            for (int ni = 0; ni < 4; ni++) {
                int n0 = warp_n + ni * 8 + lg;
                bf[ni][0] = Bs[n0 * NSTR + kw];
                bf[ni][1] = Bs[n0 * NSTR + kw + 4];
            }
#pragma unroll
            for (int mi = 0; mi < 2; mi++)
#pragma unroll
                for (int ni = 0; ni < 4; ni++)
                    mma16n8k16(c[mi][ni][0], c[mi][ni][1], c[mi][ni][2], c[mi][ni][3],
                               af[mi][0], af[mi][1], af[mi][2], af[mi][3],
                               bf[ni][0], bf[ni][1]);
        }
        __syncthreads();
    }

#pragma unroll
    for (int mi = 0; mi < 2; mi++)
#pragma unroll
        for (int half = 0; half < 2; half++) {
            int m = mbase + warp_m + mi * 16 + lg + half * 8;
#pragma unroll
            for (int ni = 0; ni < 4; ni++) {
                int col = nbase + warp_n + ni * 8 + 2 * lt;
                *(float2*)&out[(size_t)m * 256 + col] =
                    make_float2(c[mi][ni][2 * half + 0], c[mi][ni][2 * half + 1]);
            }
        }
}

// ---------------- FUSED edge layer: 512 thr, LDSM, double-buffered ---------
#define EF_DSMEM (2 * (64 * HSTR) * 4 + 2 * (256 * HSTR) * 4)
__global__ void __launch_bounds__(512)
edge_fused(const float* __restrict__ A, const float* __restrict__ W,
           const float* __restrict__ ai, const float* __restrict__ aj,
           const float* __restrict__ mask,
           const float* __restrict__ lng, const float* __restrict__ lnb,
           const float* __restrict__ v,
           float* __restrict__ out, float* __restrict__ dotv)
{
    extern __shared__ unsigned dyn[];
    unsigned* Asb[2] = {dyn, dyn + 64 * HSTR};
    unsigned* Bsb[2] = {dyn + 2 * 64 * HSTR, dyn + 2 * 64 * HSTR + 256 * HSTR};
    float* red = (float*)dyn;

    int tid = threadIdx.x;
    int lane = tid & 31, wid = tid >> 5;
    int wm = wid & 1;
    int wn = wid >> 1;
    int warp_m = wm * 32;
    int warp_n = wn * 32;
    int mbase = blockIdx.x * 64;
    int lg = lane >> 2, lt = lane & 3;

    float c[2][4][4];
#pragma unroll
    for (int mi = 0; mi < 2; mi++)
#pragma unroll
        for (int ni = 0; ni < 4; ni++)
#pragma unroll
            for (int q = 0; q < 4; q++) c[mi][ni][q] = 0.f;

    int arow = tid >> 3;
    int akw = (tid & 7) * 2;
    const float* Ap = A + (size_t)(mbase + arow) * 256 + akw * 2;
    const float* Wp = W + (size_t)arow * 768 + akw * 2;

    uint32_t abase[2] = {smem_u32(Asb[0]), smem_u32(Asb[1])};
    uint32_t bbase[2] = {smem_u32(Bsb[0]), smem_u32(Bsb[1])};
    uint32_t a_off = (uint32_t)(warp_m + (lane & 15)) * HROWB + (lane >> 4) * 16;
    uint32_t b_off = (uint32_t)(warp_n + ((lane >> 4) << 3) + (lane & 7)) * HROWB
                   + ((lane >> 3) & 1) * 16;

    {
        float4 ra = *(const float4*)Ap;
        *(uint2*)&Asb[0][arow * HSTR + akw] = f2h4(ra);
#pragma unroll
        for (int rr = 0; rr < 4; rr++) {
            float4 rb = *(const float4*)(Wp + (size_t)rr * 64 * 768);
            *(uint2*)&Bsb[0][(rr * 64 + arow) * HSTR + akw] = f2h4(rb);
        }
    }
    __syncthreads();

    int cur = 0;
    for (int kt = 0; kt < 256; kt += 32) {
        bool more = (kt + 32) < 256;
        float4 ra; float4 rb[4];
        if (more) {
            ra = *(const float4*)(Ap + kt + 32);
#pragma unroll
            for (int rr = 0; rr < 4; rr++)
                rb[rr] = *(const float4*)(Wp + (size_t)rr * 64 * 768 + kt + 32);
        }
        unsigned af[2][2][4], bf[2][2][4];
#pragma unroll
        for (int mi = 0; mi < 2; mi++)
#pragma unroll
            for (int ks = 0; ks < 2; ks++)
                ldsm_x4(af[mi][ks], abase[cur] + a_off + mi * 16 * HROWB + ks * 32);
#pragma unroll
        for (int p = 0; p < 2; p++)
#pragma unroll
            for (int ks = 0; ks < 2; ks++)
                ldsm_x4(bf[p][ks], bbase[cur] + b_off + p * 16 * HROWB + ks * 32);
#pragma unroll
        for (int ks = 0; ks < 2; ks++)
#pragma unroll
            for (int mi = 0; mi < 2; mi++)
#pragma unroll
                for (int p = 0; p < 2; p++) {
                    mma16n8k16(c[mi][2*p][0], c[mi][2*p][1], c[mi][2*p][2], c[mi][2*p][3],
                               af[mi][ks][0], af[mi][ks][1], af[mi][ks][2], af[mi][ks][3],
                               bf[p][ks][0], bf[p][ks][1]);
                    mma16n8k16(c[mi][2*p+1][0], c[mi][2*p+1][1], c[mi][2*p+1][2], c[mi][2*p+1][3],
                               af[mi][ks][0], af[mi][ks][1], af[mi][ks][2], af[mi][ks][3],
                               bf[p][ks][2], bf[p][ks][3]);
                }
        if (more) {
            int nxt = cur ^ 1;
            *(uint2*)&Asb[nxt][arow * HSTR + akw] = f2h4(ra);
#pragma unroll
            for (int rr = 0; rr < 4; rr++)
                *(uint2*)&Bsb[nxt][(rr * 64 + arow) * HSTR + akw] = f2h4(rb[rr]);
        }
        __syncthreads();
        cur ^= 1;
    }

    // ---- epilogue phase 1
#pragma unroll
    for (int mi = 0; mi < 2; mi++) {
#pragma unroll
        for (int half = 0; half < 2; half++) {
            int rloc = warp_m + mi * 16 + half * 8 + lg;
            int m = mbase + rloc;
            int b = m >> 14;
            int i = (m >> 7) & 127;
            int j = m & 127;
            float mv = mask[m];
            const float* aip = &ai[(size_t)((b << 7) + i) * 256];
            const float* ajp = &aj[(size_t)((b << 7) + j) * 256];
            const float* res = &A[(size_t)m * 256];
            float rs = 0.f, rq = 0.f;
#pragma unroll
            for (int ni = 0; ni < 4; ni++) {
                int col = warp_n + ni * 8 + 2 * lt;
                float2 a2 = *(const float2*)&aip[col];
                float2 j2 = *(const float2*)&ajp[col];
                float2 r2 = *(const float2*)&res[col];
                float v0 = c[mi][ni][2 * half + 0] + a2.x + j2.x;
                float v1 = c[mi][ni][2 * half + 1] + a2.y + j2.y;
                v0 = (v0 > 0.f ? v0 : ALPHA * v0) * mv + r2.x;
                v1 = (v1 > 0.f ? v1 : ALPHA * v1) * mv + r2.y;
                c[mi][ni][2 * half + 0] = v0;
                c[mi][ni][2 * half + 1] = v1;
                rs += v0 + v1;
                rq += v0 * v0 + v1 * v1;
            }
            rs += __shfl_xor_sync(0xffffffffu, rs, 1);
            rs += __shfl_xor_sync(0xffffffffu, rs, 2);
            rq += __shfl_xor_sync(0xffffffffu, rq, 1);
            rq += __shfl_xor_sync(0xffffffffu, rq, 2);
            if (lt == 0) {
                red[wn * 64 + rloc] = rs;
                red[512 + wn * 64 + rloc] = rq;
            }
        }
    }
    __syncthreads();
    if (tid < 64) {
        float S = 0.f, Q = 0.f;
#pragma unroll
        for (int w8 = 0; w8 < 8; w8++) {
            S += red[w8 * 64 + tid];
            Q += red[512 + w8 * 64 + tid];
        }
        float mean = S * (1.f / 256.f);
        float var = Q * (1.f / 256.f) - mean * mean;
        red[1024 + tid] = mean;
        red[1088 + tid] = rsqrtf(var + LN_EPS);
    }
    __syncthreads();

    // ---- epilogue phase 2
#pragma unroll
    for (int mi = 0; mi < 2; mi++) {
#pragma unroll
        for (int half = 0; half < 2; half++) {
            int rloc = warp_m + mi * 16 + half * 8 + lg;
            int m = mbase + rloc;
            float mean = red[1024 + rloc];
            float inv = red[1088 + rloc];
            float dvp = 0.f;
#pragma unroll
            for (int ni = 0; ni < 4; ni++) {
                int col = warp_n + ni * 8 + 2 * lt;
                float2 g2 = *(const float2*)&lng[col];
                float2 b2 = *(const float2*)&lnb[col];
                float2 v2 = *(const float2*)&v[col];
                float y0 = (c[mi][ni][2 * half + 0] - mean) * inv * g2.x + b2.x;
                float y1 = (c[mi][ni][2 * half + 1] - mean) * inv * g2.y + b2.y;
                *(float2*)&out[(size_t)m * 256 + col] = make_float2(y0, y1);
                dvp += y0 * v2.x + y1 * v2.y;
            }
            dvp += __shfl_xor_sync(0xffffffffu, dvp, 1);
            dvp += __shfl_xor_sync(0xffffffffu, dvp, 2);
            if (lt == 0) red[wn * 64 + rloc] = dvp;
        }
    }
    __syncthreads();
    if (tid < 64) {
        float S = 0.f;
#pragma unroll
        for (int w8 = 0; w8 < 8; w8++) S += red[w8 * 64 + tid];
        dotv[mbase + tid] = S;
    }
}

// ---------------- PARALLEL vw: v = Wbp^T ub, w = Wfp^T ub ------------------
// grid 8 x 256 thr: block b owns k in [32b, 32b+32); thread = (k-lane, c-slice)
__global__ void vw_kernel(const float* __restrict__ Wbp, const float* __restrict__ Wfp,
                          const float* __restrict__ ub,
                          float* __restrict__ v, float* __restrict__ w)
{
    __shared__ float sva[8][32];
    __shared__ float swa[8][32];
    int kk = blockIdx.x * 32 + (threadIdx.x & 31);
    int cs = threadIdx.x >> 5;          // 0..7, covers c = cs*32..+32
    float a = 0.f, b = 0.f;
#pragma unroll
    for (int q = 0; q < 32; q++) {
        int c = cs * 32 + q;
        float u = ub[c];
        a += u * Wbp[c * 256 + kk];
        b += u * Wfp[c * 256 + kk];
    }
    sva[cs][threadIdx.x & 31] = a;
    swa[cs][threadIdx.x & 31] = b;
    __syncthreads();
    if (threadIdx.x < 32) {
        float A = 0.f, B = 0.f;
#pragma unroll
        for (int q = 0; q < 8; q++) { A += sva[q][threadIdx.x]; B += swa[q][threadIdx.x]; }
        v[kk] = A;
        w[kk] = B;
    }
}

// ---------------- s[r] = nodes[r]·w : grid 32 x 256 (warp per row) ---------
__global__ void s_kernel(const float* __restrict__ nodes, const float* __restrict__ w,
                         float* __restrict__ s)
{
    int warp = threadIdx.x >> 5, lane = threadIdx.x & 31;
    int row = blockIdx.x * 8 + warp;          // grid 32 * 8 warps = 256 rows
    const float* rp = nodes + (size_t)row * 256;
    float acc = 0.f;
#pragma unroll
    for (int q = 0; q < 8; q++) acc += rp[lane + q * 32] * w[lane + q * 32];
#pragma unroll
    for (int o = 16; o; o >>= 1) acc += __shfl_xor_sync(0xffffffffu, acc, o);
    if (lane == 0) s[row] = acc;
}

// ---------------- attention + node update (LN fused) -----------------------
__global__ void __launch_bounds__(256)
attn_kernel(const float* __restrict__ dotv, const float* __restrict__ s,
            const float* __restrict__ nf, const float* __restrict__ mask,
            const float* __restrict__ nodes_old, const float* __restrict__ g,
            const float* __restrict__ bt, float* __restrict__ nodes_new)
{
    int bi = blockIdx.x;
    int b = bi >> 7, i = bi & 127;
    int t = threadIdx.x;
    __shared__ float sm_a[128];
    __shared__ float sred1[8], sred2[8];
    __shared__ float sm_m, sm_sum, sm_mean, sm_inv;

    if (t < 128) {
        int j = t;
        float mv = mask[b * 16384 + i * 128 + j];
        float r;
        if (mv > 0.f) {
            float dv = dotv[b * 16384 + j * 128 + i];
            r = dv + s[b * 128 + i] + s[b * 128 + j];
            r = r > 0.f ? r : ALPHA * r;
        } else {
            r = NEG_BIG;
        }
        sm_a[j] = r;
    }
    __syncthreads();
    if (t < 32) {
        float m = fmaxf(fmaxf(sm_a[t], sm_a[t + 32]), fmaxf(sm_a[t + 64], sm_a[t + 96]));
#pragma unroll
        for (int o = 16; o; o >>= 1) m = fmaxf(m, __shfl_xor_sync(0xffffffffu, m, o));
        if (t == 0) sm_m = m;
    }
    __syncthreads();
    if (t < 128) sm_a[t] = expf(sm_a[t] - sm_m);
    __syncthreads();
    if (t < 32) {
        float su = sm_a[t] + sm_a[t + 32] + sm_a[t + 64] + sm_a[t + 96];
#pragma unroll
        for (int o = 16; o; o >>= 1) su += __shfl_xor_sync(0xffffffffu, su, o);
        if (t == 0) sm_sum = su;
    }
    __syncthreads();
    float inv_sum = 1.f / sm_sum;

    int c = t;
    float acc = 0.f;
    const float* nfb = nf + (size_t)b * Nn * Cc + c;
#pragma unroll 4
    for (int j = 0; j < 128; j++) acc += sm_a[j] * nfb[(size_t)j * Cc];
    acc *= inv_sum;
    float h = (acc > 0.f ? acc : ALPHA * acc) + nodes_old[(size_t)(b * 128 + i) * 256 + c];

    int lane = t & 31, wp = t >> 5;
    float su = h, sq = h * h;
#pragma unroll
    for (int o = 16; o; o >>= 1) {
        su += __shfl_xor_sync(0xffffffffu, su, o);
        sq += __shfl_xor_sync(0xffffffffu, sq, o);
    }
    if (lane == 0) { sred1[wp] = su; sred2[wp] = sq; }
    __syncthreads();
    if (t == 0) {
        float S = 0.f, Q = 0.f;
#pragma unroll
        for (int w2 = 0; w2 < 8; w2++) { S += sred1[w2]; Q += sred2[w2]; }
        float mean = S * (1.f / 256.f);
        float var = Q * (1.f / 256.f) - mean * mean;
        sm_mean = mean;
        sm_inv = rsqrtf(var + LN_EPS);
    }
    __syncthreads();
    nodes_new[(size_t)(b * 128 + i) * 256 + c] = (h - sm_mean) * sm_inv * g[c] + bt[c];
}

// ---------------- edge logits: out[row,k] = e[row]·ecW[k] + ecb[k] ---------
__global__ void edge_logits_kernel(const float* __restrict__ e, const float* __restrict__ W,
                                   const float* __restrict__ bias, float* __restrict__ out)
{
    int warp = threadIdx.x >> 5, lane = threadIdx.x & 31;
    int row = blockIdx.x * 8 + warp;
    const float* rp = e + (size_t)row * 256;
    float x[8];
#pragma unroll
    for (int q = 0; q < 8; q++) x[q] = rp[lane + q * 32];
#pragma unroll
    for (int k = 0; k < KE_; k++) {
        float acc = 0.f;
#pragma unroll
        for (int q = 0; q < 8; q++) acc += x[q] * W[k * 256 + lane + q * 32];
#pragma unroll
        for (int o = 16; o; o >>= 1) acc += __shfl_xor_sync(0xffffffffu, acc, o);
        if (lane == 0) out[(size_t)row * KE_ + k] = acc + bias[k];
    }
}

// ---------------- host ------------------------------------------------------
extern "C" void kernel_launch(void* const* d_in, const int* in_sizes, int n_in,
                              void* d_out, int out_size)
{
    const float* nodes_in = (const float*)d_in[0];
    const float* edges_in = (const float*)d_in[1];
    const float* adj      = (const float*)d_in[2];
    const float* pnW = (const float*)d_in[3];
    const float* pnb = (const float*)d_in[4];
    const float* peW = (const float*)d_in[5];
    const float* peb = (const float*)d_in[6];
    const float* Wb  = (const float*)d_in[7];
    const float* Wbp = (const float*)d_in[8];
    const float* Wfp = (const float*)d_in[9];
    const float* ub  = (const float*)d_in[10];
    const float* Wf  = (const float*)d_in[11];
    const float* eln_g = (const float*)d_in[12];
    const float* eln_b = (const float*)d_in[13];
    const float* nln_g = (const float*)d_in[14];
    const float* nln_b = (const float*)d_in[15];
    const float* ncW = (const float*)d_in[16];
    const float* ncb = (const float*)d_in[17];
    const float* ecW = (const float*)d_in[18];
    const float* ecb = (const float*)d_in[19];

    float *eA, *eB, *n0, *n1, *ai_, *aj_, *nf_, *s_, *v_, *w_, *dv_;
    cudaGetSymbolAddress((void**)&eA, g_eA);
    cudaGetSymbolAddress((void**)&eB, g_eB);
    cudaGetSymbolAddress((void**)&n0, g_n0);
    cudaGetSymbolAddress((void**)&n1, g_n1);
    cudaGetSymbolAddress((void**)&ai_, g_ai);
    cudaGetSymbolAddress((void**)&aj_, g_aj);
    cudaGetSymbolAddress((void**)&nf_, g_nf);
    cudaGetSymbolAddress((void**)&s_, g_s);
    cudaGetSymbolAddress((void**)&v_, g_v);
    cudaGetSymbolAddress((void**)&w_, g_w);
    cudaGetSymbolAddress((void**)&dv_, g_dotv);

    cudaFuncSetAttribute(edge_fused, cudaFuncAttributeMaxDynamicSharedMemorySize,
                         EF_DSMEM);

    float* out = (float*)d_out;
    float* out_nodes = out;
    float* out_edges = out + NODES_SZ;

    // ping-pong; layer 2 writes land directly in d_out (no copies)
    float* ebuf[4] = {eA, eB, eA, out_edges};
    float* nbuf[4] = {n0, n1, n0, out_nodes};

    dim3 bs(16, 16);

    // initial projections
    gemm_small<<<dim3(16, 16), bs>>>(nodes_in, pnW, pnb, nbuf[0], 256, 256, 128, 128);
    edge_proj_mma<<<dim3(2, 256), 512>>>(edges_in, peW, 64, 64, peb, ebuf[0]);

    for (int l = 0; l < 3; l++) {
        const float* Wb_l  = Wb  + (size_t)l * 256 * 768;
        const float* Wbp_l = Wbp + (size_t)l * 65536;
        const float* Wfp_l = Wfp + (size_t)l * 65536;
        const float* ub_l  = ub  + l * 256;
        const float* Wf_l  = Wf  + (size_t)l * 65536;
        float* ecur = ebuf[l]; float* enxt = ebuf[l + 1];
        float* ncur = nbuf[l]; float* nnxt = nbuf[l + 1];

        vw_kernel<<<8, 256>>>(Wbp_l, Wfp_l, ub_l, v_, w_);
        node3_mma<<<dim3(4, 4, 3), 128>>>(ncur, Wb_l, Wf_l, ai_, aj_, nf_);
        s_kernel<<<32, 256>>>(ncur, w_, s_);

        edge_fused<<<512, 512, EF_DSMEM>>>(ecur, Wb_l + 256, ai_, aj_, adj,
                                           eln_g + l * 256, eln_b + l * 256, v_,
                                           enxt, dv_);
        attn_kernel<<<256, 256>>>(dv_, s_, nf_, adj, ncur,
                                  nln_g + l * 256, nln_b + l * 256, nnxt);
    }

    // final heads read directly from d_out regions
    gemm_small<<<dim3(7, 16), bs>>>(nbuf[3], ncW, ncb, out + NODES_SZ + EDGES_SZ,
                                    256, KN_, 256, 256);
    edge_logits_kernel<<<4096, 256>>>(ebuf[3], ecW, ecb,
                                      out + NODES_SZ + EDGES_SZ + 256 * KN_);
}

// round 17
// speedup vs baseline: 1.7234x; 1.0412x over previous
#include <cuda_runtime.h>
#include <cuda_fp16.h>
#include <cstdint>

#define Bb 2
#define Nn 128
#define Cc 256
#define BN2 (Bb*Nn*Nn)        // 32768 edge rows
#define NODES_SZ (Bb*Nn*Cc)   // 65536
#define EDGES_SZ (BN2*Cc)     // 8388608
#define KN_ 101
#define KE_ 7
#define ALPHA 0.2f
#define LN_EPS 1e-5f
#define NEG_BIG (-1e30f)

// ---------------- scratch (device globals: allocation-free) ----------------
__device__ float g_eA[EDGES_SZ];
__device__ float g_eB[EDGES_SZ];
__device__ __half g_wh[3 * Cc * Cc];   // fp16 Wb2 slices, all 3 layers
__device__ float g_n0[NODES_SZ];
__device__ float g_n1[NODES_SZ];
__device__ float g_ai[NODES_SZ];
__device__ float g_aj[NODES_SZ];
__device__ float g_nf[NODES_SZ];
__device__ float g_s[Bb*Nn];
__device__ float g_v[Cc];
__device__ float g_w[Cc];
__device__ float g_dotv[BN2];

// ---------------- fp16 helpers ---------------------------------------------
__device__ __forceinline__ uint2 f2h4(float4 v)
{
    __half2 lo = __floats2half2_rn(v.x, v.y);
    __half2 hi = __floats2half2_rn(v.z, v.w);
    uint2 r;
    r.x = *(unsigned*)&lo;
    r.y = *(unsigned*)&hi;
    return r;
}
__device__ __forceinline__ void mma16n8k16(float& c0, float& c1, float& c2, float& c3,
                                           unsigned a0, unsigned a1, unsigned a2, unsigned a3,
                                           unsigned b0, unsigned b1)
{
    asm volatile("mma.sync.aligned.m16n8k16.row.col.f32.f16.f16.f32 "
                 "{%0,%1,%2,%3}, {%4,%5,%6,%7}, {%8,%9}, {%0,%1,%2,%3};"
                 : "+f"(c0), "+f"(c1), "+f"(c2), "+f"(c3)
                 : "r"(a0), "r"(a1), "r"(a2), "r"(a3), "r"(b0), "r"(b1));
}
__device__ __forceinline__ void ldsm_x4(unsigned r[4], uint32_t addr)
{
    asm volatile("ldmatrix.sync.aligned.m8n8.x4.shared.b16 {%0,%1,%2,%3}, [%4];"
                 : "=r"(r[0]), "=r"(r[1]), "=r"(r[2]), "=r"(r[3]) : "r"(addr));
}
__device__ __forceinline__ uint32_t smem_u32(const void* p)
{
    uint32_t a;
    asm("{ .reg .u64 t; cvta.to.shared.u64 t, %1; cvt.u32.u64 %0, t; }"
        : "=r"(a) : "l"(p));
    return a;
}

// 80-byte rows (32 halves data + pad): bank walk conflict-free for LDSM
#define HSTR 20
#define HROWB 80
// scalar-LDS node kernel stride
#define NSTR 18

// ---------------- small generic GEMM: out[m,n] = A[m,:]·W[n,:] + bias ------
__global__ void gemm_small(const float* __restrict__ A, const float* __restrict__ W,
                           const float* __restrict__ bias, float* __restrict__ out,
                           int M, int N, int K, int ldw)
{
    __shared__ float As[16][16];
    __shared__ float Ws[16][17];
    int tx = threadIdx.x, ty = threadIdx.y;
    int m = blockIdx.y * 16 + ty;
    int n = blockIdx.x * 16 + tx;
    float acc = 0.f;
    for (int k0 = 0; k0 < K; k0 += 16) {
        As[ty][tx] = (m < M) ? A[m * K + k0 + tx] : 0.f;
        int nn = blockIdx.x * 16 + ty;
        Ws[ty][tx] = (nn < N) ? W[(size_t)nn * ldw + k0 + tx] : 0.f;
        __syncthreads();
#pragma unroll
        for (int kk = 0; kk < 16; kk++) acc += As[ty][kk] * Ws[tx][kk];
        __syncthreads();
    }
    if (m < M && n < N) {
        float b = bias ? bias[n] : 0.f;
        out[m * N + n] = acc + b;
    }
}

// ---------------- W -> fp16 conversion (all 3 layers, once) ----------------
__global__ void wcvt_kernel(const float* __restrict__ Wb, __half* __restrict__ wh)
{
    int idx = blockIdx.x * 256 + threadIdx.x;   // 768 blocks -> 196608
    int l = idx >> 16;
    int r = idx & 65535;
    int n = r >> 8, k = r & 255;
    wh[idx] = __float2half(Wb[(size_t)l * 256 * 768 + (size_t)n * 768 + 256 + k]);
}

// ---------------- edge projection GEMM (K=64): 512 thr, 128x128, LDSM ------
__global__ void __launch_bounds__(512)
edge_proj_mma(const float* __restrict__ A, const float* __restrict__ W,
              int K, int ldw, const float* __restrict__ bias, float* __restrict__ out)
{
    __shared__ unsigned As[128 * HSTR];
    __shared__ unsigned Bs[128 * HSTR];
    int tid = threadIdx.x;
    int lane = tid & 31, wid = tid >> 5;
    int warp_m = (wid & 3) * 32;
    int warp_n = (wid >> 2) * 32;
    int mbase = blockIdx.y * 128;
    int nbase = blockIdx.x * 128;
    int lg = lane >> 2, lt = lane & 3;

    float c[2][4][4];
#pragma unroll
    for (int mi = 0; mi < 2; mi++)
#pragma unroll
        for (int ni = 0; ni < 4; ni++)
#pragma unroll
            for (int q = 0; q < 4; q++) c[mi][ni][q] = 0.f;

    int lrow = tid >> 2;
    int lkw = (tid & 3) * 4;
    const float* Aptr = A + (size_t)(mbase + lrow) * K + lkw * 2;
    const float* Wptr = W + (size_t)(nbase + lrow) * ldw + lkw * 2;
    unsigned* asw = &As[lrow * HSTR + lkw];
    unsigned* bsw = &Bs[lrow * HSTR + lkw];

    uint32_t abase = smem_u32(As), bbase = smem_u32(Bs);
    uint32_t a_off = (uint32_t)(warp_m + (lane & 15)) * HROWB + (lane >> 4) * 16;
    uint32_t b_off = (uint32_t)(warp_n + ((lane >> 4) << 3) + (lane & 7)) * HROWB
                   + ((lane >> 3) & 1) * 16;

    float4 ra[2], rb[2];
#pragma unroll
    for (int q = 0; q < 2; q++) {
        ra[q] = *(const float4*)(Aptr + 4 * q);
        rb[q] = *(const float4*)(Wptr + 4 * q);
    }

    for (int kt = 0; kt < K; kt += 32) {
#pragma unroll
        for (int q = 0; q < 2; q++) {
            *(uint2*)(asw + 2 * q) = f2h4(ra[q]);
            *(uint2*)(bsw + 2 * q) = f2h4(rb[q]);
        }
        __syncthreads();
        if (kt + 32 < K) {
#pragma unroll
            for (int q = 0; q < 2; q++) {
                ra[q] = *(const float4*)(Aptr + kt + 32 + 4 * q);
                rb[q] = *(const float4*)(Wptr + kt + 32 + 4 * q);
            }
        }
        unsigned af[2][2][4], bf[2][2][4];
#pragma unroll
        for (int mi = 0; mi < 2; mi++)
#pragma unroll
            for (int ks = 0; ks < 2; ks++)
                ldsm_x4(af[mi][ks], abase + a_off + mi * 16 * HROWB + ks * 32);
#pragma unroll
        for (int p = 0; p < 2; p++)
#pragma unroll
            for (int ks = 0; ks < 2; ks++)
                ldsm_x4(bf[p][ks], bbase + b_off + p * 16 * HROWB + ks * 32);
#pragma unroll
        for (int ks = 0; ks < 2; ks++)
#pragma unroll
            for (int mi = 0; mi < 2; mi++)
#pragma unroll
                for (int p = 0; p < 2; p++) {
                    mma16n8k16(c[mi][2*p][0], c[mi][2*p][1], c[mi][2*p][2], c[mi][2*p][3],
                               af[mi][ks][0], af[mi][ks][1], af[mi][ks][2], af[mi][ks][3],
                               bf[p][ks][0], bf[p][ks][1]);
                    mma16n8k16(c[mi][2*p+1][0], c[mi][2*p+1][1], c[mi][2*p+1][2], c[mi][2*p+1][3],
                               af[mi][ks][0], af[mi][ks][1], af[mi][ks][2], af[mi][ks][3],
                               bf[p][ks][2], bf[p][ks][3]);
                }
        __syncthreads();
    }

#pragma unroll
    for (int mi = 0; mi < 2; mi++)
#pragma unroll
        for (int half = 0; half < 2; half++) {
            int m = mbase + warp_m + mi * 16 + lg + half * 8;
#pragma unroll
            for (int ni = 0; ni < 4; ni++) {
                int col = nbase + warp_n + ni * 8 + 2 * lt;
                float2 bv = *(const float2*)&bias[col];
                *(float2*)&out[(size_t)m * 256 + col] =
                    make_float2(c[mi][ni][2 * half + 0] + bv.x,
                                c[mi][ni][2 * half + 1] + bv.y);
            }
        }
}

// ---------------- node GEMMs: 64x64 tiles, 48 blocks, fp16 scalar-LDS ------
__global__ void __launch_bounds__(128)
node3_mma(const float* __restrict__ A, const float* __restrict__ Wb_l,
          const float* __restrict__ Wf_l,
          float* __restrict__ ai, float* __restrict__ aj, float* __restrict__ nf)
{
    __shared__ unsigned As[64 * NSTR];
    __shared__ unsigned Bs[64 * NSTR];
    int z = blockIdx.z;
    const float* W = (z == 0) ? Wb_l : (z == 1) ? (Wb_l + 512) : Wf_l;
    int ldw = (z == 2) ? 256 : 768;
    float* out = (z == 0) ? ai : (z == 1) ? aj : nf;

    int tid = threadIdx.x;
    int lane = tid & 31, wid = tid >> 5;
    int warp_m = (wid & 1) * 32;
    int warp_n = (wid >> 1) * 32;
    int mbase = blockIdx.y * 64;
    int nbase = blockIdx.x * 64;
    int lg = lane >> 2, lt = lane & 3;

    float c[2][4][4];
#pragma unroll
    for (int mi = 0; mi < 2; mi++)
#pragma unroll
        for (int ni = 0; ni < 4; ni++)
#pragma unroll
            for (int q = 0; q < 4; q++) c[mi][ni][q] = 0.f;

    int lrow = tid >> 1;
    int lkw = (tid & 1) * 8;
    const float* Aptr = A + (size_t)(mbase + lrow) * 256 + lkw * 2;
    const float* Wptr = W + (size_t)(nbase + lrow) * ldw + lkw * 2;
    unsigned* asw = &As[lrow * NSTR + lkw];
    unsigned* bsw = &Bs[lrow * NSTR + lkw];

    float4 ra[4], rb[4];
#pragma unroll
    for (int q = 0; q < 4; q++) {
        ra[q] = *(const float4*)(Aptr + 4 * q);
        rb[q] = *(const float4*)(Wptr + 4 * q);
    }

    for (int kt = 0; kt < 256; kt += 32) {
#pragma unroll
        for (int q = 0; q < 4; q++) {
            *(uint2*)(asw + 2 * q) = f2h4(ra[q]);
            *(uint2*)(bsw + 2 * q) = f2h4(rb[q]);
        }
        __syncthreads();
        if (kt + 32 < 256) {
#pragma unroll
            for (int q = 0; q < 4; q++) {
                ra[q] = *(const float4*)(Aptr + kt + 32 + 4 * q);
                rb[q] = *(const float4*)(Wptr + kt + 32 + 4 * q);
            }
        }
#pragma unroll
        for (int ks = 0; ks < 2; ks++) {
            int kw = ks * 8 + lt;
            unsigned af[2][4], bf[4][2];
#pragma unroll
            for (int mi = 0; mi < 2; mi++) {
                int r0 = warp_m + mi * 16 + lg;
                af[mi][0] = As[r0 * NSTR + kw];
                af[mi][1] = As[(r0 + 8) * NSTR + kw];
                af[mi][2] = As[r0 * NSTR + kw + 4];
                af[mi][3] = As[(r0 + 8) * NSTR + kw + 4];
            }
#pragma unroll
            for (int ni = 0; ni < 4; ni++) {
                int n0 = warp_n + ni * 8 + lg;
                bf[ni][0] = Bs[n0 * NSTR + kw];
                bf[ni][1] = Bs[n0 * NSTR + kw + 4];
            }
#pragma unroll
            for (int mi = 0; mi < 2; mi++)
#pragma unroll
                for (int ni = 0; ni < 4; ni++)
                    mma16n8k16(c[mi][ni][0], c[mi][ni][1], c[mi][ni][2], c[mi][ni][3],
                               af[mi][0], af[mi][1], af[mi][2], af[mi][3],
                               bf[ni][0], bf[ni][1]);
        }
        __syncthreads();
    }

#pragma unroll
    for (int mi = 0; mi < 2; mi++)
#pragma unroll
        for (int half = 0; half < 2; half++) {
            int m = mbase + warp_m + mi * 16 + lg + half * 8;
#pragma unroll
            for (int ni = 0; ni < 4; ni++) {
                int col = nbase + warp_n + ni * 8 + 2 * lt;
                *(float2*)&out[(size_t)m * 256 + col] =
                    make_float2(c[mi][ni][2 * half + 0], c[mi][ni][2 * half + 1]);
            }
        }
}

// ---------------- FUSED edge layer: 512 thr, LDSM, dbl-buffer, fp16 W ------
#define EF_DSMEM (2 * (64 * HSTR) * 4 + 2 * (256 * HSTR) * 4)
__global__ void __launch_bounds__(512)
edge_fused(const float* __restrict__ A, const __half* __restrict__ Wh,
           const float* __restrict__ ai, const float* __restrict__ aj,
           const float* __restrict__ mask,
           const float* __restrict__ lng, const float* __restrict__ lnb,
           const float* __restrict__ v,
           float* __restrict__ out, float* __restrict__ dotv)
{
    extern __shared__ unsigned dyn[];
    unsigned* Asb[2] = {dyn, dyn + 64 * HSTR};
    unsigned* Bsb[2] = {dyn + 2 * 64 * HSTR, dyn + 2 * 64 * HSTR + 256 * HSTR};
    float* red = (float*)dyn;

    int tid = threadIdx.x;
    int lane = tid & 31, wid = tid >> 5;
    int wm = wid & 1;
    int wn = wid >> 1;
    int warp_m = wm * 32;
    int warp_n = wn * 32;
    int mbase = blockIdx.x * 64;
    int lg = lane >> 2, lt = lane & 3;

    float c[2][4][4];
#pragma unroll
    for (int mi = 0; mi < 2; mi++)
#pragma unroll
        for (int ni = 0; ni < 4; ni++)
#pragma unroll
            for (int q = 0; q < 4; q++) c[mi][ni][q] = 0.f;

    int arow = tid >> 3;             // 0..63
    int akw = (tid & 7) * 2;         // half2-word offset 0..14 (half idx = akw*2)
    const float* Ap = A + (size_t)(mbase + arow) * 256 + akw * 2;
    const __half* Wp = Wh + (size_t)arow * 256 + akw * 2;   // fp16, row stride 256

    uint32_t abase[2] = {smem_u32(Asb[0]), smem_u32(Asb[1])};
    uint32_t bbase[2] = {smem_u32(Bsb[0]), smem_u32(Bsb[1])};
    uint32_t a_off = (uint32_t)(warp_m + (lane & 15)) * HROWB + (lane >> 4) * 16;
    uint32_t b_off = (uint32_t)(warp_n + ((lane >> 4) << 3) + (lane & 7)) * HROWB
                   + ((lane >> 3) & 1) * 16;

    {
        float4 ra = *(const float4*)Ap;
        *(uint2*)&Asb[0][arow * HSTR + akw] = f2h4(ra);
#pragma unroll
        for (int rr = 0; rr < 4; rr++) {
            uint2 rb = *(const uint2*)(Wp + (size_t)rr * 64 * 256);
            *(uint2*)&Bsb[0][(rr * 64 + arow) * HSTR + akw] = rb;
        }
    }
    __syncthreads();

    int cur = 0;
    for (int kt = 0; kt < 256; kt += 32) {
        bool more = (kt + 32) < 256;
        float4 ra; uint2 rb[4];
        if (more) {
            ra = *(const float4*)(Ap + kt + 32);
#pragma unroll
            for (int rr = 0; rr < 4; rr++)
                rb[rr] = *(const uint2*)(Wp + (size_t)rr * 64 * 256 + kt + 32);
        }
        unsigned af[2][2][4], bf[2][2][4];
#pragma unroll
        for (int mi = 0; mi < 2; mi++)
#pragma unroll
            for (int ks = 0; ks < 2; ks++)
                ldsm_x4(af[mi][ks], abase[cur] + a_off + mi * 16 * HROWB + ks * 32);
#pragma unroll
        for (int p = 0; p < 2; p++)
#pragma unroll
            for (int ks = 0; ks < 2; ks++)
                ldsm_x4(bf[p][ks], bbase[cur] + b_off + p * 16 * HROWB + ks * 32);
#pragma unroll
        for (int ks = 0; ks < 2; ks++)
#pragma unroll
            for (int mi = 0; mi < 2; mi++)
#pragma unroll
                for (int p = 0; p < 2; p++) {
                    mma16n8k16(c[mi][2*p][0], c[mi][2*p][1], c[mi][2*p][2], c[mi][2*p][3],
                               af[mi][ks][0], af[mi][ks][1], af[mi][ks][2], af[mi][ks][3],
                               bf[p][ks][0], bf[p][ks][1]);
                    mma16n8k16(c[mi][2*p+1][0], c[mi][2*p+1][1], c[mi][2*p+1][2], c[mi][2*p+1][3],
                               af[mi][ks][0], af[mi][ks][1], af[mi][ks][2], af[mi][ks][3],
                               bf[p][ks][2], bf[p][ks][3]);
                }
        if (more) {
            int nxt = cur ^ 1;
            *(uint2*)&Asb[nxt][arow * HSTR + akw] = f2h4(ra);
#pragma unroll
            for (int rr = 0; rr < 4; rr++)
                *(uint2*)&Bsb[nxt][(rr * 64 + arow) * HSTR + akw] = rb[rr];
        }
        __syncthreads();
        cur ^= 1;
    }

    // ---- epilogue phase 1
#pragma unroll
    for (int mi = 0; mi < 2; mi++) {
#pragma unroll
        for (int half = 0; half < 2; half++) {
            int rloc = warp_m + mi * 16 + half * 8 + lg;
            int m = mbase + rloc;
            int b = m >> 14;
            int i = (m >> 7) & 127;
            int j = m & 127;
            float mv = mask[m];
            const float* aip = &ai[(size_t)((b << 7) + i) * 256];
            const float* ajp = &aj[(size_t)((b << 7) + j) * 256];
            const float* res = &A[(size_t)m * 256];
            float rs = 0.f, rq = 0.f;
#pragma unroll
            for (int ni = 0; ni < 4; ni++) {
                int col = warp_n + ni * 8 + 2 * lt;
                float2 a2 = *(const float2*)&aip[col];
                float2 j2 = *(const float2*)&ajp[col];
                float2 r2 = *(const float2*)&res[col];
                float v0 = c[mi][ni][2 * half + 0] + a2.x + j2.x;
                float v1 = c[mi][ni][2 * half + 1] + a2.y + j2.y;
                v0 = (v0 > 0.f ? v0 : ALPHA * v0) * mv + r2.x;
                v1 = (v1 > 0.f ? v1 : ALPHA * v1) * mv + r2.y;
                c[mi][ni][2 * half + 0] = v0;
                c[mi][ni][2 * half + 1] = v1;
                rs += v0 + v1;
                rq += v0 * v0 + v1 * v1;
            }
            rs += __shfl_xor_sync(0xffffffffu, rs, 1);
            rs += __shfl_xor_sync(0xffffffffu, rs, 2);
            rq += __shfl_xor_sync(0xffffffffu, rq, 1);
            rq += __shfl_xor_sync(0xffffffffu, rq, 2);
            if (lt == 0) {
                red[wn * 64 + rloc] = rs;
                red[512 + wn * 64 + rloc] = rq;
            }
        }
    }
    __syncthreads();
    if (tid < 64) {
        float S = 0.f, Q = 0.f;
#pragma unroll
        for (int w8 = 0; w8 < 8; w8++) {
            S += red[w8 * 64 + tid];
            Q += red[512 + w8 * 64 + tid];
        }
        float mean = S * (1.f / 256.f);
        float var = Q * (1.f / 256.f) - mean * mean;
        red[1024 + tid] = mean;
        red[1088 + tid] = rsqrtf(var + LN_EPS);
    }
    __syncthreads();

    // ---- epilogue phase 2
#pragma unroll
    for (int mi = 0; mi < 2; mi++) {
#pragma unroll
        for (int half = 0; half < 2; half++) {
            int rloc = warp_m + mi * 16 + half * 8 + lg;
            int m = mbase + rloc;
            float mean = red[1024 + rloc];
            float inv = red[1088 + rloc];
            float dvp = 0.f;
#pragma unroll
            for (int ni = 0; ni < 4; ni++) {
                int col = warp_n + ni * 8 + 2 * lt;
                float2 g2 = *(const float2*)&lng[col];
                float2 b2 = *(const float2*)&lnb[col];
                float2 v2 = *(const float2*)&v[col];
                float y0 = (c[mi][ni][2 * half + 0] - mean) * inv * g2.x + b2.x;
                float y1 = (c[mi][ni][2 * half + 1] - mean) * inv * g2.y + b2.y;
                *(float2*)&out[(size_t)m * 256 + col] = make_float2(y0, y1);
                dvp += y0 * v2.x + y1 * v2.y;
            }
            dvp += __shfl_xor_sync(0xffffffffu, dvp, 1);
            dvp += __shfl_xor_sync(0xffffffffu, dvp, 2);
            if (lt == 0) red[wn * 64 + rloc] = dvp;
        }
    }
    __syncthreads();
    if (tid < 64) {
        float S = 0.f;
#pragma unroll
        for (int w8 = 0; w8 < 8; w8++) S += red[w8 * 64 + tid];
        dotv[mbase + tid] = S;
    }
}

// ---------------- PARALLEL vw: v = Wbp^T ub, w = Wfp^T ub ------------------
__global__ void vw_kernel(const float* __restrict__ Wbp, const float* __restrict__ Wfp,
                          const float* __restrict__ ub,
                          float* __restrict__ v, float* __restrict__ w)
{
    __shared__ float sva[8][32];
    __shared__ float swa[8][32];
    int kk = blockIdx.x * 32 + (threadIdx.x & 31);
    int cs = threadIdx.x >> 5;
    float a = 0.f, b = 0.f;
#pragma unroll
    for (int q = 0; q < 32; q++) {
        int c = cs * 32 + q;
        float u = ub[c];
        a += u * Wbp[c * 256 + kk];
        b += u * Wfp[c * 256 + kk];
    }
    sva[cs][threadIdx.x & 31] = a;
    swa[cs][threadIdx.x & 31] = b;
    __syncthreads();
    if (threadIdx.x < 32) {
        float A = 0.f, B = 0.f;
#pragma unroll
        for (int q = 0; q < 8; q++) { A += sva[q][threadIdx.x]; B += swa[q][threadIdx.x]; }
        v[kk] = A;
        w[kk] = B;
    }
}

// ---------------- s[r] = nodes[r]·w : grid 32 x 256 (warp per row) ---------
__global__ void s_kernel(const float* __restrict__ nodes, const float* __restrict__ w,
                         float* __restrict__ s)
{
    int warp = threadIdx.x >> 5, lane = threadIdx.x & 31;
    int row = blockIdx.x * 8 + warp;
    const float* rp = nodes + (size_t)row * 256;
    float acc = 0.f;
#pragma unroll
    for (int q = 0; q < 8; q++) acc += rp[lane + q * 32] * w[lane + q * 32];
#pragma unroll
    for (int o = 16; o; o >>= 1) acc += __shfl_xor_sync(0xffffffffu, acc, o);
    if (lane == 0) s[row] = acc;
}

// ---------------- attention + node update (LN fused) -----------------------
__global__ void __launch_bounds__(256)
attn_kernel(const float* __restrict__ dotv, const float* __restrict__ s,
            const float* __restrict__ nf, const float* __restrict__ mask,
            const float* __restrict__ nodes_old, const float* __restrict__ g,
            const float* __restrict__ bt, float* __restrict__ nodes_new)
{
    int bi = blockIdx.x;
    int b = bi >> 7, i = bi & 127;
    int t = threadIdx.x;
    __shared__ float sm_a[128];
    __shared__ float sred1[8], sred2[8];
    __shared__ float sm_m, sm_sum, sm_mean, sm_inv;

    if (t < 128) {
        int j = t;
        float mv = mask[b * 16384 + i * 128 + j];
        float r;
        if (mv > 0.f) {
            float dv = dotv[b * 16384 + j * 128 + i];
            r = dv + s[b * 128 + i] + s[b * 128 + j];
            r = r > 0.f ? r : ALPHA * r;
        } else {
            r = NEG_BIG;
        }
        sm_a[j] = r;
    }
    __syncthreads();
    if (t < 32) {
        float m = fmaxf(fmaxf(sm_a[t], sm_a[t + 32]), fmaxf(sm_a[t + 64], sm_a[t + 96]));
#pragma unroll
        for (int o = 16; o; o >>= 1) m = fmaxf(m, __shfl_xor_sync(0xffffffffu, m, o));
        if (t == 0) sm_m = m;
    }
    __syncthreads();
    if (t < 128) sm_a[t] = expf(sm_a[t] - sm_m);
    __syncthreads();
    if (t < 32) {
        float su = sm_a[t] + sm_a[t + 32] + sm_a[t + 64] + sm_a[t + 96];
#pragma unroll
        for (int o = 16; o; o >>= 1) su += __shfl_xor_sync(0xffffffffu, su, o);
        if (t == 0) sm_sum = su;
    }
    __syncthreads();
    float inv_sum = 1.f / sm_sum;

    int c = t;
    float acc = 0.f;
    const float* nfb = nf + (size_t)b * Nn * Cc + c;
#pragma unroll 4
    for (int j = 0; j < 128; j++) acc += sm_a[j] * nfb[(size_t)j * Cc];
    acc *= inv_sum;
    float h = (acc > 0.f ? acc : ALPHA * acc) + nodes_old[(size_t)(b * 128 + i) * 256 + c];

    int lane = t & 31, wp = t >> 5;
    float su = h, sq = h * h;
#pragma unroll
    for (int o = 16; o; o >>= 1) {
        su += __shfl_xor_sync(0xffffffffu, su, o);
        sq += __shfl_xor_sync(0xffffffffu, sq, o);
    }
    if (lane == 0) { sred1[wp] = su; sred2[wp] = sq; }
    __syncthreads();
    if (t == 0) {
        float S = 0.f, Q = 0.f;
#pragma unroll
        for (int w2 = 0; w2 < 8; w2++) { S += sred1[w2]; Q += sred2[w2]; }
        float mean = S * (1.f / 256.f);
        float var = Q * (1.f / 256.f) - mean * mean;
        sm_mean = mean;
        sm_inv = rsqrtf(var + LN_EPS);
    }
    __syncthreads();
    nodes_new[(size_t)(b * 128 + i) * 256 + c] = (h - sm_mean) * sm_inv * g[c] + bt[c];
}

// ---------------- edge logits: out[row,k] = e[row]·ecW[k] + ecb[k] ---------
__global__ void edge_logits_kernel(const float* __restrict__ e, const float* __restrict__ W,
                                   const float* __restrict__ bias, float* __restrict__ out)
{
    int warp = threadIdx.x >> 5, lane = threadIdx.x & 31;
    int row = blockIdx.x * 8 + warp;
    const float* rp = e + (size_t)row * 256;
    float x[8];
#pragma unroll
    for (int q = 0; q < 8; q++) x[q] = rp[lane + q * 32];
#pragma unroll
    for (int k = 0; k < KE_; k++) {
        float acc = 0.f;
#pragma unroll
        for (int q = 0; q < 8; q++) acc += x[q] * W[k * 256 + lane + q * 32];
#pragma unroll
        for (int o = 16; o; o >>= 1) acc += __shfl_xor_sync(0xffffffffu, acc, o);
        if (lane == 0) out[(size_t)row * KE_ + k] = acc + bias[k];
    }
}

// ---------------- host ------------------------------------------------------
extern "C" void kernel_launch(void* const* d_in, const int* in_sizes, int n_in,
                              void* d_out, int out_size)
{
    const float* nodes_in = (const float*)d_in[0];
    const float* edges_in = (const float*)d_in[1];
    const float* adj      = (const float*)d_in[2];
    const float* pnW = (const float*)d_in[3];
    const float* pnb = (const float*)d_in[4];
    const float* peW = (const float*)d_in[5];
    const float* peb = (const float*)d_in[6];
    const float* Wb  = (const float*)d_in[7];
    const float* Wbp = (const float*)d_in[8];
    const float* Wfp = (const float*)d_in[9];
    const float* ub  = (const float*)d_in[10];
    const float* Wf  = (const float*)d_in[11];
    const float* eln_g = (const float*)d_in[12];
    const float* eln_b = (const float*)d_in[13];
    const float* nln_g = (const float*)d_in[14];
    const float* nln_b = (const float*)d_in[15];
    const float* ncW = (const float*)d_in[16];
    const float* ncb = (const float*)d_in[17];
    const float* ecW = (const float*)d_in[18];
    const float* ecb = (const float*)d_in[19];

    float *eA, *eB, *n0, *n1, *ai_, *aj_, *nf_, *s_, *v_, *w_, *dv_;
    __half* wh_;
    cudaGetSymbolAddress((void**)&eA, g_eA);
    cudaGetSymbolAddress((void**)&eB, g_eB);
    cudaGetSymbolAddress((void**)&wh_, g_wh);
    cudaGetSymbolAddress((void**)&n0, g_n0);
    cudaGetSymbolAddress((void**)&n1, g_n1);
    cudaGetSymbolAddress((void**)&ai_, g_ai);
    cudaGetSymbolAddress((void**)&aj_, g_aj);
    cudaGetSymbolAddress((void**)&nf_, g_nf);
    cudaGetSymbolAddress((void**)&s_, g_s);
    cudaGetSymbolAddress((void**)&v_, g_v);
    cudaGetSymbolAddress((void**)&w_, g_w);
    cudaGetSymbolAddress((void**)&dv_, g_dotv);

    cudaFuncSetAttribute(edge_fused, cudaFuncAttributeMaxDynamicSharedMemorySize,
                         EF_DSMEM);

    float* out = (float*)d_out;
    float* out_nodes = out;
    float* out_edges = out + NODES_SZ;

    // ping-pong; layer 2 writes land directly in d_out (no copies)
    float* ebuf[4] = {eA, eB, eA, out_edges};
    float* nbuf[4] = {n0, n1, n0, out_nodes};

    dim3 bs(16, 16);

    // weight fp16 conversion (constants; once) + initial projections
    wcvt_kernel<<<768, 256>>>(Wb, wh_);
    gemm_small<<<dim3(16, 16), bs>>>(nodes_in, pnW, pnb, nbuf[0], 256, 256, 128, 128);
    edge_proj_mma<<<dim3(2, 256), 512>>>(edges_in, peW, 64, 64, peb, ebuf[0]);

    for (int l = 0; l < 3; l++) {
        const float* Wb_l  = Wb  + (size_t)l * 256 * 768;
        const float* Wbp_l = Wbp + (size_t)l * 65536;
        const float* Wfp_l = Wfp + (size_t)l * 65536;
        const float* ub_l  = ub  + l * 256;
        const float* Wf_l  = Wf  + (size_t)l * 65536;
        float* ecur = ebuf[l]; float* enxt = ebuf[l + 1];
        float* ncur = nbuf[l]; float* nnxt = nbuf[l + 1];

        vw_kernel<<<8, 256>>>(Wbp_l, Wfp_l, ub_l, v_, w_);
        node3_mma<<<dim3(4, 4, 3), 128>>>(ncur, Wb_l, Wf_l, ai_, aj_, nf_);
        s_kernel<<<32, 256>>>(ncur, w_, s_);

        edge_fused<<<512, 512, EF_DSMEM>>>(ecur, wh_ + (size_t)l * 65536, ai_, aj_, adj,
                                           eln_g + l * 256, eln_b + l * 256, v_,
                                           enxt, dv_);
        attn_kernel<<<256, 256>>>(dv_, s_, nf_, adj, ncur,
                                  nln_g + l * 256, nln_b + l * 256, nnxt);
    }

    // final heads read directly from d_out regions
    gemm_small<<<dim3(7, 16), bs>>>(nbuf[3], ncW, ncb, out + NODES_SZ + EDGES_SZ,
                                    256, KN_, 256, 256);
    edge_logits_kernel<<<4096, 256>>>(ebuf[3], ecW, ecb,
                                      out + NODES_SZ + EDGES_SZ + 256 * KN_);
}